// round 4
// baseline (speedup 1.0000x reference)
#include <cuda_runtime.h>
#include <math.h>

#define BB 512
#define CC 256
#define NW 8                 // 256 concepts / 32 bits
#define TEMP_INV (1.0f/0.07f)
#define GRID BB

// ---- persistent scratch (no allocation allowed) ----
__device__ float    g_clip[2*BB];    // per-row (lse - diag): img rows [0..511], txt rows [512..1023]
__device__ float    g_ccl [2*BB];    // per-row bce sum [0..511], mask sum [512..1023]
__device__ float    g_kl  [BB];      // per-row KL term
__device__ unsigned g_bits[BB*NW];   // binary concept bitmasks (row-major [row][word])
__device__ int      g_cnt [BB];      // per-row positive-concept popcount
__device__ unsigned g_count = 0;     // barrier-1 arrive counter (self-resetting)
__device__ unsigned g_sense = 0;     // barrier-1 generation (monotonic across replays)
__device__ unsigned g_fin   = 0;     // barrier-2 arrive counter (block 0 resets)

// ---------- deterministic block reductions (256 threads) ----------
__device__ __forceinline__ float blockSum(float v) {
    __shared__ float sh[9];
    int tid = threadIdx.x;
    #pragma unroll
    for (int o = 16; o > 0; o >>= 1) v += __shfl_down_sync(0xffffffffu, v, o);
    __syncthreads();
    if ((tid & 31) == 0) sh[tid >> 5] = v;
    __syncthreads();
    if (tid == 0) {
        float s = 0.f;
        #pragma unroll
        for (int w = 0; w < 8; w++) s += sh[w];
        sh[8] = s;
    }
    __syncthreads();
    return sh[8];
}

__device__ __forceinline__ float blockMax(float v) {
    __shared__ float sh[9];
    int tid = threadIdx.x;
    #pragma unroll
    for (int o = 16; o > 0; o >>= 1) v = fmaxf(v, __shfl_down_sync(0xffffffffu, v, o));
    __syncthreads();
    if ((tid & 31) == 0) sh[tid >> 5] = v;
    __syncthreads();
    if (tid == 0) {
        float s = sh[0];
        #pragma unroll
        for (int w = 1; w < 8; w++) s = fmaxf(s, sh[w]);
        sh[8] = s;
    }
    __syncthreads();
    return sh[8];
}

// generation-based grid barrier (all GRID blocks must be co-resident)
__device__ __forceinline__ void grid_barrier() {
    __syncthreads();
    if (threadIdx.x == 0) {
        __threadfence();
        unsigned gen = atomicAdd(&g_sense, 0u);       // read generation BEFORE arriving
        unsigned arrived = atomicAdd(&g_count, 1u);
        if (arrived == GRID - 1) {
            g_count = 0;
            __threadfence();
            atomicAdd(&g_sense, 1u);                  // release
        } else {
            while (atomicAdd(&g_sense, 0u) == gen) {} // spin
        }
        __threadfence();
    }
    __syncthreads();
}

__global__ void __launch_bounds__(256, 4)
cca_fused_kernel(const float* __restrict__ img,
                 const float* __restrict__ txt,
                 const float* __restrict__ cl,
                 const float* __restrict__ cis,
                 const int*   __restrict__ mc,
                 float* __restrict__ out) {
    __shared__ unsigned sbits[NW * BB];   // TRANSPOSED: [word][row] -> conflict-free inner loop
    __shared__ int      scnt[BB];
    __shared__ float    scis[BB];

    const int b   = blockIdx.x;    // 0..511
    const int tid = threadIdx.x;   // 0..255

    // ================= phase 1: concept BCE + bitmasks + CLIP rows =================
    {
        int   m    = mc[(size_t)b * CC + tid];
        float x    = cl[(size_t)b * CC + tid];
        float mask = (m != -1) ? 1.f : 0.f;
        float tgt  = (m > 0)   ? 1.f : 0.f;
        float la   = (x > 0.f) ? (x + log1pf(__expf(-x))) : log1pf(__expf(x));
        float loss = (la - x * tgt) * mask;

        unsigned ball = __ballot_sync(0xffffffffu, m > 0);
        if ((tid & 31) == 0) g_bits[b * NW + (tid >> 5)] = ball;

        float ls = blockSum(loss);
        float ms = blockSum(mask);
        float pc = blockSum(tgt);
        if (tid == 0) { g_ccl[b] = ls; g_ccl[BB + b] = ms; g_cnt[b] = (int)pc; }
    }
    {
        const float* r = img + (size_t)b * BB;
        float v0 = r[tid], v1 = r[tid + 256];
        float m  = blockMax(fmaxf(v0, v1));
        float se = blockSum(__expf(v0 - m) + __expf(v1 - m));
        if (tid == 0) g_clip[b] = m + logf(se) - r[b];

        r  = txt + (size_t)b * BB;
        v0 = r[tid]; v1 = r[tid + 256];
        m  = blockMax(fmaxf(v0, v1));
        se = blockSum(__expf(v0 - m) + __expf(v1 - m));
        if (tid == 0) g_clip[BB + b] = m + logf(se) - r[b];
    }

    grid_barrier();

    // ================= phase 2: Jaccard -> softmax targets -> KL per row =================
    {
        // load bit table transposed + counts; load cis row while tracking maxc
        for (int i = tid; i < BB * NW; i += 256) {
            int row = i >> 3, w = i & (NW - 1);
            sbits[w * BB + row] = g_bits[i];
        }
        for (int i = tid; i < BB; i += 256) scnt[i] = g_cnt[i];
        float maxc = -3.402823e38f;
        for (int i = tid; i < BB; i += 256) {
            float v = cis[(size_t)b * BB + i];
            scis[i] = v;
            maxc = fmaxf(maxc, v);
        }
        maxc = blockMax(maxc);   // includes __syncthreads -> shared fills visible

        unsigned a[NW];
        #pragma unroll
        for (int w = 0; w < NW; w++) a[w] = sbits[w * BB + b];
        int   cnti = scnt[b];
        float maxs = (cnti > 0) ? TEMP_INV : 0.f;   // sim(i,i)=1 when row nonempty

        float es = 0.f, num = 0.f, ec = 0.f;
        for (int j = tid; j < BB; j += 256) {
            int inter = 0;
            #pragma unroll
            for (int w = 0; w < NW; w++)
                inter += __popc(a[w] & sbits[w * BB + j]);
            int   uni = cnti + scnt[j] - inter;
            float sim = (uni > 0) ? (float)inter / (float)uni : 0.f;
            float s   = sim * TEMP_INV;
            float cij = scis[j];
            float e   = __expf(s - maxs);
            es  += e;
            num += e * (s - cij);
            ec  += __expf(cij - maxc);
        }
        es  = blockSum(es);
        ec  = blockSum(ec);
        num = blockSum(num);
        if (tid == 0)
            // KL_i = num/Zs - maxs - log Zs + maxc + log Zc
            g_kl[b] = num / es - maxs - logf(es) + maxc + logf(ec);
    }

    // ================= phase 3: block 0 combines =================
    if (b != 0) {
        __syncthreads();
        if (tid == 0) { __threadfence(); atomicAdd(&g_fin, 1u); }
        return;
    }
    __syncthreads();
    if (tid == 0) {
        while (atomicAdd(&g_fin, 0u) != GRID - 1) {}
        g_fin = 0;                 // reset for next graph replay (launches are serialized)
        __threadfence();
    }
    __syncthreads();

    {
        float cs = 0.f, ls = 0.f, ms = 0.f, ks = 0.f;
        for (int i = tid; i < 2 * BB; i += 256) cs += g_clip[i];
        for (int i = tid; i < BB; i += 256) {
            ls += g_ccl[i];
            ms += g_ccl[BB + i];
            ks += g_kl[i];
        }
        cs = blockSum(cs);
        ls = blockSum(ls);
        ms = blockSum(ms);
        ks = blockSum(ks);
        if (tid == 0) {
            float clip_loss = cs / (2.f * BB);
            float bce_loss  = ls / (ms + 1e-8f);
            float kl_loss   = ks / (float)BB;
            out[0] = clip_loss + 0.5f * bce_loss + 0.3f * kl_loss;
        }
    }
}

extern "C" void kernel_launch(void* const* d_in, const int* in_sizes, int n_in,
                              void* d_out, int out_size) {
    const float* img = (const float*)d_in[0];   // logits_per_image [512,512]
    const float* txt = (const float*)d_in[1];   // logits_per_text  [512,512]
    const float* cl  = (const float*)d_in[2];   // concepts_logits  [512,256]
    const float* cis = (const float*)d_in[3];   // concepts_image_similarity [512,512]
    const int*   mc  = (const int*)d_in[4];     // medical_concepts [512,256]
    float* out = (float*)d_out;

    cca_fused_kernel<<<GRID, 256>>>(img, txt, cl, cis, mc, out);
}